// round 1
// baseline (speedup 1.0000x reference)
#include <cuda_runtime.h>

// Window attention: B_=8192 windows, N=49 tokens, C=256, H=8, hd=32, nW=1024.
// Fully fused: one CTA per window. qkv GEMM -> per-head attention -> proj GEMM,
// all intermediates in shared memory.

#define N_TOK   49
#define CDIM    256
#define HEADS   8
#define HD      32
#define Q_SCALE 0.17677669529663687f   // 32^-0.5

// ---- shared memory layout (float offsets) ----
// s_x   : [49][256] input tile, later reused as attention output [49][256]
// s_q   : [8][49][32] scaled Q
// s_kT  : [8][32][49] K transposed (d-major)
// s_v   : [8][49][32] V
// s_mask: [49][49]  -100*mask (float)
// union : weight tile Ws[8][256] (GEMM phases)  OR  S[56*49]+m[56]+sum[56] (attention)
#define OFF_X     0
#define OFF_Q     12544
#define OFF_KT    25088
#define OFF_V     37632
#define OFF_MASK  50176
#define OFF_UNION 52578              // even -> 8B aligned for paired loads
#define OFF_S     OFF_UNION
#define OFF_M     (OFF_UNION + 2744) // 56*49
#define OFF_SUM   (OFF_M + 56)
#define SMEM_FLOATS (OFF_UNION + 2856)
#define SMEM_BYTES  (SMEM_FLOATS * 4)   // 221,736 B  < 227 KB carveout

// ---- packed dual-fp32 helpers (sm_100+) ----
__device__ __forceinline__ unsigned long long pack2(float lo, float hi) {
    unsigned long long r;
    asm("mov.b64 %0, {%1, %2};" : "=l"(r) : "f"(lo), "f"(hi));
    return r;
}
__device__ __forceinline__ void unpack2(unsigned long long v, float& lo, float& hi) {
    asm("mov.b64 {%0, %1}, %2;" : "=f"(lo), "=f"(hi) : "l"(v));
}
__device__ __forceinline__ unsigned long long fma2(unsigned long long a,
                                                   unsigned long long b,
                                                   unsigned long long c) {
    unsigned long long d;
    asm("fma.rn.f32x2 %0, %1, %2, %3;" : "=l"(d) : "l"(a), "l"(b), "l"(c));
    return d;
}

extern __shared__ float sm[];

__global__ void __launch_bounds__(256, 1)
winattn_kernel(const float* __restrict__ x,
               const int*   __restrict__ mask,
               const float* __restrict__ qkv_w,   // [256][768]
               const float* __restrict__ qkv_b,   // [768]
               const float* __restrict__ proj_w,  // [256][256]
               const float* __restrict__ proj_b,  // [256]
               const float* __restrict__ bias_table, // [169][8]
               float*       __restrict__ out,
               int nW)
{
    const int b   = blockIdx.x;
    const int tid = threadIdx.x;
    const int tx  = tid & 31;      // 0..31
    const int ty  = tid >> 5;      // 0..7

    // ---------------- Phase 1: load x tile and mask ----------------
    {
        const float* xg = x + (size_t)b * (N_TOK * CDIM);
        for (int i = tid; i < N_TOK * CDIM; i += 256) sm[OFF_X + i] = xg[i];
        const int* mg = mask + (size_t)(b % nW) * (N_TOK * N_TOK);
        for (int i = tid; i < N_TOK * N_TOK; i += 256)
            sm[OFF_MASK + i] = -100.0f * (float)mg[i];
    }
    __syncthreads();

    // ---------------- Phase 2: qkv = x @ qkv_w + qkv_b ----------------
    // Per 256-col chunk (q, k, v). Thread (ty,tx): rows n = ty*7+i (i<7, n<49),
    // col pairs c = {tx*2 + 64j, +1} (j<4). Weight tile Ws[8][256] streamed via
    // SMEM with register prefetch.
    for (int ch = 0; ch < 3; ch++) {
        const int c0 = ch << 8;
        unsigned long long acc[7][4];
        #pragma unroll
        for (int i = 0; i < 7; i++)
            #pragma unroll
            for (int j = 0; j < 4; j++) acc[i][j] = 0ULL;

        float wreg[8];
        #pragma unroll
        for (int r = 0; r < 8; r++)
            wreg[r] = qkv_w[(size_t)r * 768 + c0 + tid];

        for (int kb = 0; kb < 256; kb += 8) {
            __syncthreads();   // previous tile consumed
            #pragma unroll
            for (int r = 0; r < 8; r++)
                sm[OFF_UNION + r * 256 + tid] = wreg[r];
            __syncthreads();
            if (kb + 8 < 256) {
                #pragma unroll
                for (int r = 0; r < 8; r++)
                    wreg[r] = qkv_w[(size_t)(kb + 8 + r) * 768 + c0 + tid];
            }
            #pragma unroll
            for (int kk = 0; kk < 8; kk++) {
                unsigned long long w2[4];
                #pragma unroll
                for (int j = 0; j < 4; j++)
                    w2[j] = *(const unsigned long long*)
                            &sm[OFF_UNION + kk * 256 + tx * 2 + j * 64];
                #pragma unroll
                for (int i = 0; i < 7; i++) {
                    float xv = sm[OFF_X + (ty * 7 + i) * 256 + kb + kk];
                    unsigned long long x2 = pack2(xv, xv);
                    #pragma unroll
                    for (int j = 0; j < 4; j++)
                        acc[i][j] = fma2(x2, w2[j], acc[i][j]);
                }
            }
        }
        // epilogue: +bias, scatter into q / kT / v smem
        #pragma unroll
        for (int j = 0; j < 4; j++) {
            const int c  = tx * 2 + j * 64;       // local col, even
            const int h  = c >> 5;
            const int d  = c & 31;
            const float b0 = qkv_b[c0 + c];
            const float b1 = qkv_b[c0 + c + 1];
            #pragma unroll
            for (int i = 0; i < 7; i++) {
                const int n = ty * 7 + i;
                if (n < N_TOK) {
                    float v0, v1;
                    unpack2(acc[i][j], v0, v1);
                    v0 += b0; v1 += b1;
                    if (ch == 0) {
                        v0 *= Q_SCALE; v1 *= Q_SCALE;
                        *(unsigned long long*)&sm[OFF_Q + h * 1568 + n * 32 + d]
                            = pack2(v0, v1);
                    } else if (ch == 1) {
                        sm[OFF_KT + h * 1568 + d * 49 + n]       = v0;
                        sm[OFF_KT + h * 1568 + (d + 1) * 49 + n] = v1;
                    } else {
                        *(unsigned long long*)&sm[OFF_V + h * 1568 + n * 32 + d]
                            = pack2(v0, v1);
                    }
                }
            }
        }
    }
    __syncthreads();

    // ---------------- Phase 3: attention per head ----------------
    float* S = sm + OFF_S;
    for (int h = 0; h < HEADS; h++) {
        // (a) S[p][q] = Q[p]·K[q]  (Q pre-scaled); (b) + bias + mask
        {
            const int q  = tid & 63;   // key index (valid < 49)
            const int pb = tid >> 6;   // 0..3
            float acc[13];
            #pragma unroll
            for (int i = 0; i < 13; i++) acc[i] = 0.0f;
            const float* KT = sm + OFF_KT + h * 1568;
            const float* Qs = sm + OFF_Q  + h * 1568;
            if (q < N_TOK) {
                #pragma unroll
                for (int d = 0; d < 32; d += 4) {
                    const float k0 = KT[(d    ) * 49 + q];
                    const float k1 = KT[(d + 1) * 49 + q];
                    const float k2 = KT[(d + 2) * 49 + q];
                    const float k3 = KT[(d + 3) * 49 + q];
                    #pragma unroll
                    for (int i = 0; i < 13; i++) {
                        const int p = pb + 4 * i;
                        float4 qv = *(const float4*)&Qs[p * 32 + d];
                        acc[i] = fmaf(qv.x, k0,
                                 fmaf(qv.y, k1,
                                 fmaf(qv.z, k2,
                                 fmaf(qv.w, k3, acc[i]))));
                    }
                }
                #pragma unroll
                for (int i = 0; i < 13; i++) {
                    const int p = pb + 4 * i;
                    if (p < N_TOK) {
                        // reference: idx = 13*((px-qx)+(py-qy)+12), table-gather CLAMPED
                        int dsum = (p % 7 - q % 7) + (p / 7 - q / 7) + 12;
                        int idx  = dsum * 13;
                        if (idx > 168) idx = 168;
                        S[p * 49 + q] = acc[i] + bias_table[idx * 8 + h]
                                      + sm[OFF_MASK + p * 49 + q];
                    }
                }
            }
        }
        __syncthreads();
        // (c) row max (4 threads/row, shfl reduce)
        {
            int p = tid >> 2; if (p > 48) p = 48;
            const int j = tid & 3;
            float m = -1e30f;
            for (int qq = j; qq < N_TOK; qq += 4) m = fmaxf(m, S[p * 49 + qq]);
            m = fmaxf(m, __shfl_xor_sync(0xffffffffu, m, 1));
            m = fmaxf(m, __shfl_xor_sync(0xffffffffu, m, 2));
            if (j == 0) sm[OFF_M + p] = m;
        }
        __syncthreads();
        // (d) exponentiate in place
        for (int e = tid; e < N_TOK * N_TOK; e += 256) {
            const int p = e / 49;
            S[e] = __expf(S[e] - sm[OFF_M + p]);
        }
        __syncthreads();
        // (e) row sum
        {
            int p = tid >> 2; if (p > 48) p = 48;
            const int j = tid & 3;
            float s = 0.0f;
            for (int qq = j; qq < N_TOK; qq += 4) s += S[p * 49 + qq];
            s += __shfl_xor_sync(0xffffffffu, s, 1);
            s += __shfl_xor_sync(0xffffffffu, s, 2);
            if (j == 0) sm[OFF_SUM + p] = s;
        }
        __syncthreads();
        // (f) O[p][d] = (S[p]·V[:,d]) / sum[p]  -> overwrite s_x columns h*32..+31
        {
            const int d  = tid & 31;
            const int pw = tid >> 5;   // 0..7
            float acc[7];
            #pragma unroll
            for (int i = 0; i < 7; i++) acc[i] = 0.0f;
            const float* V = sm + OFF_V + h * 1568;
            for (int qq = 0; qq < N_TOK; qq++) {
                const float vv = V[qq * 32 + d];
                #pragma unroll
                for (int i = 0; i < 7; i++) {
                    const int p = pw + 8 * i;        // up to 55; S region padded to 56 rows
                    acc[i] = fmaf(S[p * 49 + qq], vv, acc[i]);
                }
            }
            #pragma unroll
            for (int i = 0; i < 7; i++) {
                const int p = pw + 8 * i;
                if (p < N_TOK) {
                    const float inv = 1.0f / sm[OFF_SUM + p];
                    sm[OFF_X + p * 256 + h * 32 + d] = acc[i] * inv;
                }
            }
        }
        __syncthreads();
    }

    // ---------------- Phase 4: out = attnO @ proj_w + proj_b ----------------
    {
        unsigned long long acc[7][4];
        #pragma unroll
        for (int i = 0; i < 7; i++)
            #pragma unroll
            for (int j = 0; j < 4; j++) acc[i][j] = 0ULL;

        float wreg[8];
        #pragma unroll
        for (int r = 0; r < 8; r++)
            wreg[r] = proj_w[(size_t)r * 256 + tid];

        for (int kb = 0; kb < 256; kb += 8) {
            __syncthreads();
            #pragma unroll
            for (int r = 0; r < 8; r++)
                sm[OFF_UNION + r * 256 + tid] = wreg[r];
            __syncthreads();
            if (kb + 8 < 256) {
                #pragma unroll
                for (int r = 0; r < 8; r++)
                    wreg[r] = proj_w[(size_t)(kb + 8 + r) * 256 + tid];
            }
            #pragma unroll
            for (int kk = 0; kk < 8; kk++) {
                unsigned long long w2[4];
                #pragma unroll
                for (int j = 0; j < 4; j++)
                    w2[j] = *(const unsigned long long*)
                            &sm[OFF_UNION + kk * 256 + tx * 2 + j * 64];
                #pragma unroll
                for (int i = 0; i < 7; i++) {
                    float xv = sm[OFF_X + (ty * 7 + i) * 256 + kb + kk];
                    unsigned long long x2 = pack2(xv, xv);
                    #pragma unroll
                    for (int j = 0; j < 4; j++)
                        acc[i][j] = fma2(x2, w2[j], acc[i][j]);
                }
            }
        }
        float* og = out + (size_t)b * (N_TOK * CDIM);
        #pragma unroll
        for (int j = 0; j < 4; j++) {
            const int c  = tx * 2 + j * 64;
            const float b0 = proj_b[c];
            const float b1 = proj_b[c + 1];
            #pragma unroll
            for (int i = 0; i < 7; i++) {
                const int n = ty * 7 + i;
                if (n < N_TOK) {
                    float v0, v1;
                    unpack2(acc[i][j], v0, v1);
                    *(unsigned long long*)&og[n * 256 + c] = pack2(v0 + b0, v1 + b1);
                }
            }
        }
    }
}

extern "C" void kernel_launch(void* const* d_in, const int* in_sizes, int n_in,
                              void* d_out, int out_size)
{
    const float* x          = (const float*)d_in[0];
    const int*   mask       = (const int*)  d_in[1];
    const float* qkv_w      = (const float*)d_in[2];
    const float* qkv_b      = (const float*)d_in[3];
    const float* proj_w     = (const float*)d_in[4];
    const float* proj_b     = (const float*)d_in[5];
    const float* bias_table = (const float*)d_in[6];

    const int B  = in_sizes[0] / (N_TOK * CDIM);   // 8192
    const int nW = in_sizes[1] / (N_TOK * N_TOK);  // 1024

    cudaFuncSetAttribute(winattn_kernel,
                         cudaFuncAttributeMaxDynamicSharedMemorySize, SMEM_BYTES);
    winattn_kernel<<<B, 256, SMEM_BYTES>>>(x, mask, qkv_w, qkv_b,
                                           proj_w, proj_b, bias_table,
                                           (float*)d_out, nW);
}

// round 4
// speedup vs baseline: 1.1519x; 1.1519x over previous
#include <cuda_runtime.h>

// Fused Swin window attention. One CTA (256 thr) per window (B=8192).
// Phase2/4: fp32x2 packed GEMMs. Phase3: warp-per-head attention.

#define N_TOK   49
#define CDIM    256
#define Q_SCALE 0.17677669529663687f   // 32^-0.5

typedef unsigned long long ull;

// ---- shared layout (float offsets) ----
// region A: Q[8][49][32], KT[8][32][49], V[8][49][32]   (phase 3 inputs)
//           Q region reused as attention-output O[49][256] for phase 4.
// region S: per-warp S tiles [8][49*50]  (phase 3)
//           reused as x tile [49][256] + weight tile Ws[16][256] (phases 1/2/4)
// mask    : u8 [49*49] at tail
#define OFF_Q   0
#define OFF_KT  12544
#define OFF_V   25088
#define OFF_S   37632
#define OFF_XS  OFF_S
#define OFF_WS  (OFF_S + 12544)
#define S_WSTRIDE 2450                   // 49 rows * 50
#define MASK_BYTE_OFF 228928             // (OFF_S + 8*2450)*4
#define SMEM_BYTES 231360                // mask + pad, < 232448 limit

__device__ __forceinline__ ull pack2(float lo, float hi) {
    ull r; asm("mov.b64 %0, {%1, %2};" : "=l"(r) : "f"(lo), "f"(hi)); return r;
}
__device__ __forceinline__ void unpack2(ull v, float& lo, float& hi) {
    asm("mov.b64 {%0, %1}, %2;" : "=f"(lo), "=f"(hi) : "l"(v));
}
__device__ __forceinline__ ull fma2(ull a, ull b, ull c) {
    ull d; asm("fma.rn.f32x2 %0, %1, %2, %3;" : "=l"(d) : "l"(a), "l"(b), "l"(c));
    return d;
}

extern __shared__ float sm[];

// 49x256 @ 256xK-chunk GEMM: acc[7][4] f32x2 pairs per thread.
// W: gmem weights, ldw = row stride. xrow: smem [49+pad][256] activations.
__device__ __forceinline__ void gemm_49x256(const float* __restrict__ W, int ldw,
                                            const float* __restrict__ xrow,
                                            ull acc[7][4], int tid, int tx, int ty)
{
    float wreg[16];
    #pragma unroll
    for (int r = 0; r < 16; r++) wreg[r] = W[(size_t)r * ldw + tid];

    for (int kb = 0; kb < 256; kb += 16) {
        __syncthreads();                       // previous tile fully consumed
        #pragma unroll
        for (int r = 0; r < 16; r++) sm[OFF_WS + r * 256 + tid] = wreg[r];
        __syncthreads();
        if (kb + 16 < 256) {
            #pragma unroll
            for (int r = 0; r < 16; r++)
                wreg[r] = W[(size_t)(kb + 16 + r) * ldw + tid];
        }
        #pragma unroll
        for (int half = 0; half < 2; half++) {
            float xr[7][8];
            #pragma unroll
            for (int i = 0; i < 7; i++) {
                float4 t0 = *(const float4*)&xrow[(ty * 7 + i) * 256 + kb + half * 8];
                float4 t1 = *(const float4*)&xrow[(ty * 7 + i) * 256 + kb + half * 8 + 4];
                xr[i][0] = t0.x; xr[i][1] = t0.y; xr[i][2] = t0.z; xr[i][3] = t0.w;
                xr[i][4] = t1.x; xr[i][5] = t1.y; xr[i][6] = t1.z; xr[i][7] = t1.w;
            }
            #pragma unroll
            for (int kk = 0; kk < 8; kk++) {
                ull w2[4];
                #pragma unroll
                for (int j = 0; j < 4; j++)
                    w2[j] = *(const ull*)&sm[OFF_WS + (half * 8 + kk) * 256 + tx * 2 + j * 64];
                #pragma unroll
                for (int i = 0; i < 7; i++) {
                    ull x2 = pack2(xr[i][kk], xr[i][kk]);
                    #pragma unroll
                    for (int j = 0; j < 4; j++)
                        acc[i][j] = fma2(x2, w2[j], acc[i][j]);
                }
            }
        }
    }
}

__global__ void __launch_bounds__(256, 1)
winattn_kernel(const float* __restrict__ x,
               const int*   __restrict__ mask,
               const float* __restrict__ qkv_w,
               const float* __restrict__ qkv_b,
               const float* __restrict__ proj_w,
               const float* __restrict__ proj_b,
               const float* __restrict__ bias_table,
               float*       __restrict__ out,
               int nW)
{
    const int b   = blockIdx.x;
    const int tid = threadIdx.x;
    const int tx  = tid & 31;
    const int ty  = tid >> 5;

    // ---------------- Phase 1: stage x (float4) and mask (u8) ----------------
    {
        const float4* xg = (const float4*)(x + (size_t)b * (N_TOK * CDIM));
        float4* xs4 = (float4*)(sm + OFF_XS);
        for (int i = tid; i < (N_TOK * CDIM) / 4; i += 256) xs4[i] = xg[i];
        const int* mg = mask + (size_t)(b % nW) * (N_TOK * N_TOK);
        unsigned char* smask = (unsigned char*)sm + MASK_BYTE_OFF;
        for (int i = tid; i < N_TOK * N_TOK; i += 256)
            smask[i] = (unsigned char)mg[i];
    }
    // (first barrier inside gemm_49x256 orders these writes)

    // ---------------- Phase 2: qkv GEMM, scatter to Q / KT / V ----------------
    for (int ch = 0; ch < 3; ch++) {
        ull acc[7][4];
        #pragma unroll
        for (int i = 0; i < 7; i++)
            #pragma unroll
            for (int j = 0; j < 4; j++) acc[i][j] = 0ULL;

        gemm_49x256(qkv_w + (ch << 8), 768, sm + OFF_XS, acc, tid, tx, ty);

        #pragma unroll
        for (int j = 0; j < 4; j++) {
            const int c = tx * 2 + j * 64;
            const int h = c >> 5;
            const int d = c & 31;
            const float b0 = qkv_b[(ch << 8) + c];
            const float b1 = qkv_b[(ch << 8) + c + 1];
            #pragma unroll
            for (int i = 0; i < 7; i++) {
                const int n = ty * 7 + i;
                if (n < N_TOK) {
                    float v0, v1; unpack2(acc[i][j], v0, v1);
                    v0 += b0; v1 += b1;
                    if (ch == 0) {
                        *(ull*)&sm[OFF_Q + h * 1568 + n * 32 + d]
                            = pack2(v0 * Q_SCALE, v1 * Q_SCALE);
                    } else if (ch == 1) {
                        sm[OFF_KT + h * 1568 + d * 49 + n]       = v0;
                        sm[OFF_KT + h * 1568 + (d + 1) * 49 + n] = v1;
                    } else {
                        *(ull*)&sm[OFF_V + h * 1568 + n * 32 + d] = pack2(v0, v1);
                    }
                }
            }
        }
    }
    __syncthreads();   // Q/KT/V complete; x tile now dead (S overwrites it)

    // ---------------- Phase 3a: per-warp QK^T + bias + mask + softmax ----------
    {
        const int h = ty;
        const float* Qh  = sm + OFF_Q  + h * 1568;
        const float* KTh = sm + OFF_KT + h * 1568;
        float* Sw = sm + OFF_S + h * S_WSTRIDE;
        const unsigned char* smask = (const unsigned char*)sm + MASK_BYTE_OFF;

        const int q1v = 32 + tx;
        const bool v1 = (q1v < N_TOK);
        const int qq1 = v1 ? q1v : (N_TOK - 1);

        float k0[32], k1[32];
        #pragma unroll
        for (int d = 0; d < 32; d++) {
            k0[d] = KTh[d * 49 + tx];
            k1[d] = KTh[d * 49 + qq1];
        }
        const int qm0 = tx % 7,  qd0 = tx / 7;
        const int qm1 = qq1 % 7, qd1 = qq1 / 7;

        for (int p = 0; p < N_TOK; p++) {
            float a0 = 0.f, a1 = 0.f, b0a = 0.f, b1a = 0.f;
            #pragma unroll
            for (int d4 = 0; d4 < 8; d4++) {
                float4 qv = *(const float4*)&Qh[p * 32 + d4 * 4];
                if (d4 & 1) {
                    b0a = fmaf(qv.x, k0[d4*4+0], b0a); b0a = fmaf(qv.y, k0[d4*4+1], b0a);
                    b0a = fmaf(qv.z, k0[d4*4+2], b0a); b0a = fmaf(qv.w, k0[d4*4+3], b0a);
                    b1a = fmaf(qv.x, k1[d4*4+0], b1a); b1a = fmaf(qv.y, k1[d4*4+1], b1a);
                    b1a = fmaf(qv.z, k1[d4*4+2], b1a); b1a = fmaf(qv.w, k1[d4*4+3], b1a);
                } else {
                    a0 = fmaf(qv.x, k0[d4*4+0], a0); a0 = fmaf(qv.y, k0[d4*4+1], a0);
                    a0 = fmaf(qv.z, k0[d4*4+2], a0); a0 = fmaf(qv.w, k0[d4*4+3], a0);
                    a1 = fmaf(qv.x, k1[d4*4+0], a1); a1 = fmaf(qv.y, k1[d4*4+1], a1);
                    a1 = fmaf(qv.z, k1[d4*4+2], a1); a1 = fmaf(qv.w, k1[d4*4+3], a1);
                }
            }
            const int pm = p % 7, pd = p / 7;
            int i0 = ((pm - qm0) + (pd - qd0) + 12) * 13; if (i0 > 168) i0 = 168;
            int i1 = ((pm - qm1) + (pd - qd1) + 12) * 13; if (i1 > 168) i1 = 168;
            const float bias0 = __ldg(&bias_table[i0 * 8 + h]);
            const float bias1 = __ldg(&bias_table[i1 * 8 + h]);
            const float m0 = (float)smask[p * 49 + tx];
            const float m1 = (float)smask[p * 49 + qq1];

            float s0 = (a0 + b0a) + bias0 - 100.0f * m0;
            float s1 = v1 ? (a1 + b1a) + bias1 - 100.0f * m1 : -1e30f;

            float mx = fmaxf(s0, s1);
            #pragma unroll
            for (int o = 16; o; o >>= 1)
                mx = fmaxf(mx, __shfl_xor_sync(0xffffffffu, mx, o));
            float e0 = __expf(s0 - mx);
            float e1 = v1 ? __expf(s1 - mx) : 0.0f;
            float ssum = e0 + e1;
            #pragma unroll
            for (int o = 16; o; o >>= 1)
                ssum += __shfl_xor_sync(0xffffffffu, ssum, o);
            const float inv = __fdividef(1.0f, ssum);
            Sw[p * 50 + tx] = e0 * inv;
            if (v1) Sw[p * 50 + q1v] = e1 * inv;
        }
    }
    __syncthreads();   // all S done; Q region now dead -> becomes O

    // ---------------- Phase 3b: per-warp S @ V -> O[49][256] (at OFF_Q) -------
    {
        const int h = ty;
        const float* Vh = sm + OFF_V + h * 1568;
        const float* Sw = sm + OFF_S + h * S_WSTRIDE;
        float* O = sm + OFF_Q;

        float vr[49];
        #pragma unroll
        for (int q = 0; q < 49; q++) vr[q] = Vh[q * 32 + tx];

        for (int p = 0; p < N_TOK; p++) {
            float acc0 = 0.f, acc1 = 0.f;
            #pragma unroll
            for (int q2 = 0; q2 < 24; q2++) {
                float2 sp = *(const float2*)&Sw[p * 50 + q2 * 2];
                acc0 = fmaf(sp.x, vr[2 * q2],     acc0);
                acc1 = fmaf(sp.y, vr[2 * q2 + 1], acc1);
            }
            acc0 = fmaf(Sw[p * 50 + 48], vr[48], acc0);
            O[p * 256 + h * 32 + tx] = acc0 + acc1;
        }
    }
    // (first barrier inside phase-4 gemm orders O writes vs Ws/O reads)

    // ---------------- Phase 4: out = O @ proj_w + proj_b ----------------------
    {
        ull acc[7][4];
        #pragma unroll
        for (int i = 0; i < 7; i++)
            #pragma unroll
            for (int j = 0; j < 4; j++) acc[i][j] = 0ULL;

        gemm_49x256(proj_w, 256, sm + OFF_Q, acc, tid, tx, ty);

        float* og = out + (size_t)b * (N_TOK * CDIM);
        #pragma unroll
        for (int j = 0; j < 4; j++) {
            const int c = tx * 2 + j * 64;
            const float b0 = proj_b[c];
            const float b1 = proj_b[c + 1];
            #pragma unroll
            for (int i = 0; i < 7; i++) {
                const int n = ty * 7 + i;
                if (n < N_TOK) {
                    float v0, v1; unpack2(acc[i][j], v0, v1);
                    *(ull*)&og[n * 256 + c] = pack2(v0 + b0, v1 + b1);
                }
            }
        }
    }
}

extern "C" void kernel_launch(void* const* d_in, const int* in_sizes, int n_in,
                              void* d_out, int out_size)
{
    const float* x          = (const float*)d_in[0];
    const int*   mask       = (const int*)  d_in[1];
    const float* qkv_w      = (const float*)d_in[2];
    const float* qkv_b      = (const float*)d_in[3];
    const float* proj_w     = (const float*)d_in[4];
    const float* proj_b     = (const float*)d_in[5];
    const float* bias_table = (const float*)d_in[6];

    const int B  = in_sizes[0] / (N_TOK * CDIM);
    const int nW = in_sizes[1] / (N_TOK * N_TOK);

    cudaFuncSetAttribute(winattn_kernel,
                         cudaFuncAttributeMaxDynamicSharedMemorySize, SMEM_BYTES);
    winattn_kernel<<<B, 256, SMEM_BYTES>>>(x, mask, qkv_w, qkv_b,
                                           proj_w, proj_b, bias_table,
                                           (float*)d_out, nW);
}